// round 16
// baseline (speedup 1.0000x reference)
#include <cuda_runtime.h>

// ---------------------------------------------------------------------------
// Model_38225208935040: multi-region perturbed PINN forward.
//
// Algebraic collapse: mean over each symmetric perturbation grid of
// wave(base + delta) = Cd * wave(base), with
//   Cd_j = prod_d [ (1/s) * sum_i cos(lin_i * W1[d, j]) ]
// So 496 embedding evals/point -> 1 wave(base) + 3 precomputed 64-vectors.
//
// R16: K2 instruction diet. GEMV inner loops blocked by k-quads (LDS.128
// feeds 8 FFMA2 per point: layer0 LDS 256->64/thread), reduce phases
// vectorized (8 LDS.128 + STS.128 vs 32 LDS + 4 STS). Mapping unchanged
// from R13 (k-split 8, 8 pts/thread). K1 = R15.
// ---------------------------------------------------------------------------

#define PPB1 16        // K1 points per block
#define PPB2 16        // K2 points per block
#define NTHREADS 256
#define EPAD 260       // esh row stride (1040B, multiple of 16)
#define HPAD 68        // hsh row stride (272B, multiple of 16)
#define MAXN 4096

typedef unsigned long long ull;

__device__ float4 g_e[MAXN * 64];   // intermediate features [n][64] float4

__device__ __forceinline__ ull packf2(float lo, float hi) {
    ull d;
    asm("mov.b64 %0, {%1, %2};" : "=l"(d)
        : "r"(__float_as_uint(lo)), "r"(__float_as_uint(hi)));
    return d;
}
__device__ __forceinline__ void ffma2(ull& d, ull a, ull b) {
    asm("fma.rn.f32x2 %0, %1, %2, %0;" : "+l"(d) : "l"(a), "l"(b));
}
__device__ __forceinline__ float2 unpackf2(ull v) {
    unsigned int lo, hi;
    asm("mov.b64 {%0, %1}, %2;" : "=r"(lo), "=r"(hi) : "l"(v));
    return make_float2(__uint_as_float(lo), __uint_as_float(hi));
}

// ======================= Kernel 1: embed + mix (R15) =======================
__global__ void __launch_bounds__(NTHREADS) embed_mix_kernel(
    const float* __restrict__ x, const float* __restrict__ y, const float* __restrict__ t,
    const float* __restrict__ W1, const float* __restrict__ b1,
    const float* __restrict__ ewa, const float* __restrict__ ewb,
    const float* __restrict__ W2, const float* __restrict__ b2,
    const float* __restrict__ mW1, const float* __restrict__ mb1,
    const float* __restrict__ mwa, const float* __restrict__ mwb,
    const float* __restrict__ mW2, const float* __restrict__ pmb2,
    int npts)
{
    __shared__ float  cdsh[3][64];
    __shared__ float  wcsh[4];
    __shared__ float4 swc[PPB1][64];

    const int tid = threadIdx.x;
    const int base_pt = blockIdx.x * PPB1;

    if (tid < 192) {
        int r = tid >> 6;
        int j = tid & 63;
        const int   S[3] = {3, 5, 7};
        const float R[3] = {0.01f, 0.05f, 0.09f};
        int s = S[r];
        float rr = R[r];
        float inv = 1.0f / (float)s;
        float step = 2.0f * rr / (float)(s - 1);
        float prod = 1.0f;
        #pragma unroll
        for (int d = 0; d < 3; d++) {
            float w = W1[d * 64 + j];
            float c = 1.0f;
            for (int i = 0; i < (s >> 1); i++)
                c += 2.0f * __cosf((step * (float)i - rr) * w);
            prod *= c * inv;
        }
        cdsh[r][j] = prod;
    } else if (tid < 194) {
        int l = tid - 192;
        float a = (l == 0) ? ewa[0] : mwa[0];
        float b = (l == 0) ? ewb[0] : mwb[0];
        wcsh[2 * l]     = sqrtf(a * a + b * b);
        wcsh[2 * l + 1] = atan2f(b, a);
    }
    __syncthreads();

    {
        const float Ae = wcsh[0], pe = wcsh[1];
        #pragma unroll
        for (int it = 0; it < 4; it++) {
            int i  = tid + it * NTHREADS;
            int pt = i >> 6;
            int j  = i & 63;
            int n  = base_pt + pt;
            if (n >= npts) n = npts - 1;
            float xv = x[n], yv = y[n], tv = t[n];
            float z = fmaf(xv, W1[j], fmaf(yv, W1[64 + j], fmaf(tv, W1[128 + j], b1[j])));
            float w = Ae * __sinf(z + pe);
            swc[pt][j] = make_float4(w, cdsh[0][j] * w, cdsh[1][j] * w, cdsh[2][j] * w);
        }
    }
    __syncthreads();

    {
        const int q  = tid & 63;
        const int pg = tid >> 6;
        const float4* __restrict__ W2v = (const float4*)W2;
        ull A[4][4][2];
        #pragma unroll
        for (int p = 0; p < 4; p++)
            #pragma unroll
            for (int c = 0; c < 4; c++) {
                A[p][c][0] = 0ull; A[p][c][1] = 0ull;
            }

        #pragma unroll 4
        for (int j = 0; j < 64; j++) {
            float4 w = W2v[j * 64 + q];
            ull wx = packf2(w.x, w.x);
            ull wy = packf2(w.y, w.y);
            ull wz = packf2(w.z, w.z);
            ull ww = packf2(w.w, w.w);
            #pragma unroll
            for (int p = 0; p < 4; p++) {
                float4 cv = swc[pg + 4 * p][j];
                ull clo = packf2(cv.x, cv.y), chi = packf2(cv.z, cv.w);
                ffma2(A[p][0][0], clo, wx); ffma2(A[p][0][1], chi, wx);
                ffma2(A[p][1][0], clo, wy); ffma2(A[p][1][1], chi, wy);
                ffma2(A[p][2][0], clo, wz); ffma2(A[p][2][1], chi, wz);
                ffma2(A[p][3][0], clo, ww); ffma2(A[p][3][1], chi, ww);
            }
        }

        const float4 b2q = ((const float4*)b2)[q];
        const float Am = wcsh[2], pm = wcsh[3], mb2v = pmb2[0];
        #pragma unroll
        for (int p = 0; p < 4; p++) {
            float4 ef;
            #pragma unroll
            for (int c = 0; c < 4; c++) {
                float bc = (c == 0) ? b2q.x : (c == 1) ? b2q.y : (c == 2) ? b2q.z : b2q.w;
                float2 r01 = unpackf2(A[p][c][0]);
                float2 r23 = unpackf2(A[p][c][1]);
                float s0 = r01.x + bc, s1 = r01.y + bc,
                      s2 = r23.x + bc, s3 = r23.y + bc;
                float e = mb2v;
                #pragma unroll
                for (int h = 0; h < 8; h++) {
                    float z = fmaf(s0, mW1[h],
                              fmaf(s1, mW1[8 + h],
                              fmaf(s2, mW1[16 + h],
                              fmaf(s3, mW1[24 + h], mb1[h] + pm))));
                    e = fmaf(__sinf(z), Am * mW2[h], e);
                }
                ((float*)&ef)[c] = e;
            }
            int n = base_pt + pg + 4 * p;
            if (n < npts) g_e[n * 64 + q] = ef;
        }
    }
}

// ======================= Kernel 2: out MLP (R13 map + vector LDS) ==========
__global__ void __launch_bounds__(NTHREADS) out_mlp_kernel(
    const float* __restrict__ W0, const float* __restrict__ b0,
    const float* __restrict__ wa0, const float* __restrict__ wb0,
    const float* __restrict__ Wh, const float* __restrict__ bh,
    const float* __restrict__ wah, const float* __restrict__ wbh,
    const float* __restrict__ Wf1, const float* __restrict__ bf1,
    const float* __restrict__ waf, const float* __restrict__ wbf,
    const float* __restrict__ Wf2, const float* __restrict__ bf2,
    float* __restrict__ out, int npts)
{
    __shared__ float  wcsh[10];
    __shared__ __align__(16) float esh[PPB2][EPAD];
    __shared__ __align__(16) float hsh[PPB2][HPAD];
    __shared__ float4 pshare[8][PPB2][16];

    const int tid = threadIdx.x;
    const int base_pt = blockIdx.x * PPB2;

    if (tid < 5) {
        float a, b;
        switch (tid) {
            case 0: a = wa0[0]; b = wb0[0]; break;
            case 1: a = wah[0]; b = wbh[0]; break;
            case 2: a = wah[1]; b = wbh[1]; break;
            case 3: a = wah[2]; b = wbh[2]; break;
            default: a = waf[0]; b = wbf[0]; break;
        }
        wcsh[2 * tid]     = sqrtf(a * a + b * b);
        wcsh[2 * tid + 1] = atan2f(b, a);
    }

    {
        #pragma unroll
        for (int it = 0; it < 4; it++) {
            int i  = tid + it * NTHREADS;
            int pt = i >> 6;
            int q  = i & 63;
            int n  = base_pt + pt;
            if (n >= npts) n = npts - 1;
            float4 v = g_e[n * 64 + q];
            *(float4*)&esh[pt][4 * q] = v;
        }
    }
    __syncthreads();

    // GEMV mapping: f4 = tid&15, pq = (tid>>4)&1 (pts pq+2p, p=0..7),
    // g = tid>>5 (warp-uniform k-group of 32).
    // Reduce mapping: ptR = tid>>4, fr = tid&15 (one output quad/thread).
    const int f4 = tid & 15;
    const int pq = (tid >> 4) & 1;
    const int g  = tid >> 5;
    const int ptR = tid >> 4;
    const int fr  = tid & 15;

    // layer 0: 256 -> 64 (k split 8 x 32, k-quad blocked)
    {
        const float4* __restrict__ W0v = (const float4*)W0;  // [256][16] float4
        ull acc[8][2];
        #pragma unroll
        for (int p = 0; p < 8; p++) { acc[p][0] = 0ull; acc[p][1] = 0ull; }
        #pragma unroll 2
        for (int kq = 0; kq < 8; kq++) {
            int k0 = g * 32 + 4 * kq;
            float4 w0q = W0v[(k0 + 0) * 16 + f4];
            float4 w1q = W0v[(k0 + 1) * 16 + f4];
            float4 w2q = W0v[(k0 + 2) * 16 + f4];
            float4 w3q = W0v[(k0 + 3) * 16 + f4];
            ull w0lo = packf2(w0q.x, w0q.y), w0hi = packf2(w0q.z, w0q.w);
            ull w1lo = packf2(w1q.x, w1q.y), w1hi = packf2(w1q.z, w1q.w);
            ull w2lo = packf2(w2q.x, w2q.y), w2hi = packf2(w2q.z, w2q.w);
            ull w3lo = packf2(w3q.x, w3q.y), w3hi = packf2(w3q.z, w3q.w);
            #pragma unroll
            for (int p = 0; p < 8; p++) {
                float4 ev = *(const float4*)&esh[pq + 2 * p][k0];  // LDS.128
                ull e0 = packf2(ev.x, ev.x);
                ull e1 = packf2(ev.y, ev.y);
                ull e2 = packf2(ev.z, ev.z);
                ull e3 = packf2(ev.w, ev.w);
                ffma2(acc[p][0], w0lo, e0); ffma2(acc[p][1], w0hi, e0);
                ffma2(acc[p][0], w1lo, e1); ffma2(acc[p][1], w1hi, e1);
                ffma2(acc[p][0], w2lo, e2); ffma2(acc[p][1], w2hi, e2);
                ffma2(acc[p][0], w3lo, e3); ffma2(acc[p][1], w3hi, e3);
            }
        }
        #pragma unroll
        for (int p = 0; p < 8; p++) {
            float2 lo = unpackf2(acc[p][0]);
            float2 hi = unpackf2(acc[p][1]);
            pshare[g][pq + 2 * p][f4] = make_float4(lo.x, lo.y, hi.x, hi.y);
        }
        __syncthreads();
        // vectorized reduce: one (pt, f-quad) per thread
        {
            const float A0 = wcsh[0], p0 = wcsh[1];
            float4 s = pshare[0][ptR][fr];
            #pragma unroll
            for (int G = 1; G < 8; G++) {
                float4 v = pshare[G][ptR][fr];
                s.x += v.x; s.y += v.y; s.z += v.z; s.w += v.w;
            }
            float4 bq = ((const float4*)b0)[fr];
            float4 hv;
            hv.x = A0 * __sinf(s.x + bq.x + p0);
            hv.y = A0 * __sinf(s.y + bq.y + p0);
            hv.z = A0 * __sinf(s.z + bq.z + p0);
            hv.w = A0 * __sinf(s.w + bq.w + p0);
            *(float4*)&hsh[ptR][4 * fr] = hv;
        }
        __syncthreads();
    }

    // 3 hidden + final hidden: 64 -> 64 (k split 8 x 8, k-quad blocked)
    #pragma unroll 1
    for (int L = 0; L < 4; L++) {
        const float* __restrict__ Wl = (L < 3) ? (Wh + L * 4096) : Wf1;
        const float* __restrict__ bl = (L < 3) ? (bh + L * 64)   : bf1;
        const float  AL = wcsh[2 + 2 * L];
        const float  pL = wcsh[3 + 2 * L];
        const float4* __restrict__ Wv = (const float4*)Wl;   // [64][16] float4
        ull acc[8][2];
        #pragma unroll
        for (int p = 0; p < 8; p++) { acc[p][0] = 0ull; acc[p][1] = 0ull; }
        #pragma unroll
        for (int kq = 0; kq < 2; kq++) {
            int k0 = g * 8 + 4 * kq;
            float4 w0q = Wv[(k0 + 0) * 16 + f4];
            float4 w1q = Wv[(k0 + 1) * 16 + f4];
            float4 w2q = Wv[(k0 + 2) * 16 + f4];
            float4 w3q = Wv[(k0 + 3) * 16 + f4];
            ull w0lo = packf2(w0q.x, w0q.y), w0hi = packf2(w0q.z, w0q.w);
            ull w1lo = packf2(w1q.x, w1q.y), w1hi = packf2(w1q.z, w1q.w);
            ull w2lo = packf2(w2q.x, w2q.y), w2hi = packf2(w2q.z, w2q.w);
            ull w3lo = packf2(w3q.x, w3q.y), w3hi = packf2(w3q.z, w3q.w);
            #pragma unroll
            for (int p = 0; p < 8; p++) {
                float4 hvv = *(const float4*)&hsh[pq + 2 * p][k0];  // LDS.128
                ull h0 = packf2(hvv.x, hvv.x);
                ull h1 = packf2(hvv.y, hvv.y);
                ull h2 = packf2(hvv.z, hvv.z);
                ull h3 = packf2(hvv.w, hvv.w);
                ffma2(acc[p][0], w0lo, h0); ffma2(acc[p][1], w0hi, h0);
                ffma2(acc[p][0], w1lo, h1); ffma2(acc[p][1], w1hi, h1);
                ffma2(acc[p][0], w2lo, h2); ffma2(acc[p][1], w2hi, h2);
                ffma2(acc[p][0], w3lo, h3); ffma2(acc[p][1], w3hi, h3);
            }
        }
        #pragma unroll
        for (int p = 0; p < 8; p++) {
            float2 lo = unpackf2(acc[p][0]);
            float2 hi = unpackf2(acc[p][1]);
            pshare[g][pq + 2 * p][f4] = make_float4(lo.x, lo.y, hi.x, hi.y);
        }
        __syncthreads();               // partials visible; all hsh reads done
        {
            float4 s = pshare[0][ptR][fr];
            #pragma unroll
            for (int G = 1; G < 8; G++) {
                float4 v = pshare[G][ptR][fr];
                s.x += v.x; s.y += v.y; s.z += v.z; s.w += v.w;
            }
            float4 bq = ((const float4*)bl)[fr];
            float4 hv;
            hv.x = AL * __sinf(s.x + bq.x + pL);
            hv.y = AL * __sinf(s.y + bq.y + pL);
            hv.z = AL * __sinf(s.z + bq.z + pL);
            hv.w = AL * __sinf(s.w + bq.w + pL);
            *(float4*)&hsh[ptR][4 * fr] = hv;   // safe: reads done pre-barrier
        }
        __syncthreads();               // hsh writes visible for next layer
    }

    // output: 64 -> 3
    if (tid < PPB2 * 3) {
        int pt = tid / 3, f = tid % 3;
        int n = base_pt + pt;
        if (n < npts) {
            float a0 = 0.f, a1 = 0.f, a2 = 0.f, a3 = 0.f;
            #pragma unroll
            for (int i = 0; i < 16; i++) {
                a0 = fmaf(hsh[pt][4 * i + 0], Wf2[(4 * i + 0) * 3 + f], a0);
                a1 = fmaf(hsh[pt][4 * i + 1], Wf2[(4 * i + 1) * 3 + f], a1);
                a2 = fmaf(hsh[pt][4 * i + 2], Wf2[(4 * i + 2) * 3 + f], a2);
                a3 = fmaf(hsh[pt][4 * i + 3], Wf2[(4 * i + 3) * 3 + f], a3);
            }
            out[n * 3 + f] = bf2[f] + (a0 + a1) + (a2 + a3);
        }
    }
}

// ---------------------------------------------------------------------------
extern "C" void kernel_launch(void* const* d_in, const int* in_sizes, int n_in,
                              void* d_out, int out_size) {
    const float* x    = (const float*)d_in[0];
    const float* y    = (const float*)d_in[1];
    const float* t    = (const float*)d_in[2];
    const float* W1   = (const float*)d_in[3];
    const float* b1   = (const float*)d_in[4];
    const float* wa   = (const float*)d_in[5];
    const float* wb   = (const float*)d_in[6];
    const float* W2   = (const float*)d_in[7];
    const float* b2   = (const float*)d_in[8];
    const float* mW1  = (const float*)d_in[9];
    const float* mb1  = (const float*)d_in[10];
    const float* mwa  = (const float*)d_in[11];
    const float* mwb  = (const float*)d_in[12];
    const float* mW2  = (const float*)d_in[13];
    const float* mb2  = (const float*)d_in[14];
    const float* W0   = (const float*)d_in[15];
    const float* b0   = (const float*)d_in[16];
    const float* wa0  = (const float*)d_in[17];
    const float* wb0  = (const float*)d_in[18];
    const float* Wh   = (const float*)d_in[19];
    const float* bh   = (const float*)d_in[20];
    const float* wah  = (const float*)d_in[21];
    const float* wbh  = (const float*)d_in[22];
    const float* Wf1  = (const float*)d_in[23];
    const float* bf1  = (const float*)d_in[24];
    const float* waf  = (const float*)d_in[25];
    const float* wbf  = (const float*)d_in[26];
    const float* Wf2  = (const float*)d_in[27];
    const float* bf2  = (const float*)d_in[28];
    float* out = (float*)d_out;

    int npts = in_sizes[0];
    if (npts > MAXN) npts = MAXN;
    int nblocks1 = (npts + PPB1 - 1) / PPB1;
    int nblocks2 = (npts + PPB2 - 1) / PPB2;

    embed_mix_kernel<<<nblocks1, NTHREADS>>>(
        x, y, t, W1, b1, wa, wb, W2, b2,
        mW1, mb1, mwa, mwb, mW2, mb2, npts);
    out_mlp_kernel<<<nblocks2, NTHREADS>>>(
        W0, b0, wa0, wb0, Wh, bh, wah, wbh,
        Wf1, bf1, waf, wbf, Wf2, bf2,
        out, npts);
}